// round 1
// baseline (speedup 1.0000x reference)
#include <cuda_runtime.h>
#include <math.h>

#define BB   2
#define HH   512
#define WWD  512
#define CC   32
#define WIN  8
#define NT   64          // tokens per window
#define HID  128
#define NWH  (HH/WIN)    // 64
#define NWW  (WWD/WIN)   // 64
#define NTOK (BB*HH*WWD) // 524288

#define SCALE 0.17677669529663687f  // 32^-0.5
#define EPS   1e-3f
#define SLOPE 0.3f

// ---- scratch (device globals: no allocation in kernel_launch) ----
__device__ float g_x2[NTOK*CC];     // 64 MB
__device__ float g_h [NTOK*HID];    // 256 MB
__device__ float g_bias[NT*NT];

__device__ __forceinline__ float lrelu(float v){ return v >= 0.f ? v : SLOPE*v; }
__device__ __forceinline__ float gelu_exact(float v){ return v * normcdff(v); }
__device__ __forceinline__ float4 ldg4(const float* p){ return __ldg(reinterpret_cast<const float4*>(p)); }

// ---- kernel 0: gather relative-position bias matrix ----
__global__ void bias_kernel(const float* __restrict__ table, const int* __restrict__ rel_idx){
    int i = blockIdx.x*blockDim.x + threadIdx.x;
    if (i < NT*NT) g_bias[i] = table[rel_idx[i]];   // HEADS == 1
}

// ---- kernel 1: per-window fused attention + LN2 + W1 GEMM + GELU ----
// block = one window (64 threads, one per token)
__global__ __launch_bounds__(64)
void attn_kernel(const float* __restrict__ x,
                 const float* __restrict__ g1,  const float* __restrict__ beta1,
                 const float* __restrict__ Wq,  const float* __restrict__ bq,
                 const float* __restrict__ Wkv, const float* __restrict__ bkv,
                 const float* __restrict__ Wp,  const float* __restrict__ bp,
                 const float* __restrict__ g2,  const float* __restrict__ beta2,
                 const float* __restrict__ W1,  const float* __restrict__ b1m)
{
    const int w  = blockIdx.x;             // window id
    const int t  = threadIdx.x;            // token in window
    const int b  = w / (NWH*NWW);
    const int wr = w % (NWH*NWW);
    const int why = wr / NWW, wwx = wr % NWW;
    const int iy = t >> 3, jx = t & 7;
    const int gy = why*WIN + iy, gx = wwx*WIN + jx;
    const int tok = (b*HH + gy)*WWD + gx;
    const float* xrow = x + (size_t)tok*CC;

    __shared__ float ks[NT][36];           // stride 36: float4-aligned rows
    __shared__ float vs[NT][36];
    __shared__ float bsh[NT*65];           // bias transposed: bsh[m*65 + t]

    // stage bias matrix, transposed, coalesced reads, conflict-free writes
    for (int idx = t; idx < NT*NT; idx += 64){
        int r = idx >> 6, c = idx & 63;    // r = query row, c = key col
        bsh[c*65 + r] = g_bias[idx];
    }

    // ---- load x row, LayerNorm1 ----
    float xr[CC];
    #pragma unroll
    for (int c = 0; c < CC; c += 4){
        float4 v = *reinterpret_cast<const float4*>(xrow + c);
        xr[c]=v.x; xr[c+1]=v.y; xr[c+2]=v.z; xr[c+3]=v.w;
    }
    float mean = 0.f;
    #pragma unroll
    for (int c = 0; c < CC; c++) mean += xr[c];
    mean *= (1.f/CC);
    float var = 0.f;
    #pragma unroll
    for (int c = 0; c < CC; c++){ float d = xr[c]-mean; var += d*d; }
    var *= (1.f/CC);
    float rinv = rsqrtf(var + EPS);
    float xn[CC];
    #pragma unroll
    for (int c = 0; c < CC; c++)
        xn[c] = (xr[c]-mean)*rinv*__ldg(g1+c) + __ldg(beta1+c);

    // ---- q = leaky(xn @ Wq + bq) * SCALE (kept in registers) ----
    float qv[CC];
    #pragma unroll
    for (int j = 0; j < CC; j += 4){
        float4 acc = ldg4(bq + j);
        #pragma unroll
        for (int c = 0; c < CC; c++){
            float4 wv = ldg4(Wq + c*CC + j);
            float xc = xn[c];
            acc.x += xc*wv.x; acc.y += xc*wv.y; acc.z += xc*wv.z; acc.w += xc*wv.w;
        }
        qv[j]   = lrelu(acc.x)*SCALE;
        qv[j+1] = lrelu(acc.y)*SCALE;
        qv[j+2] = lrelu(acc.z)*SCALE;
        qv[j+3] = lrelu(acc.w)*SCALE;
    }
    // ---- k, v = leaky(xn @ Wkv + bkv) -> shared ----
    #pragma unroll
    for (int j = 0; j < CC; j += 4){
        float4 acc = ldg4(bkv + j);
        #pragma unroll
        for (int c = 0; c < CC; c++){
            float4 wv = ldg4(Wkv + c*(2*CC) + j);
            float xc = xn[c];
            acc.x += xc*wv.x; acc.y += xc*wv.y; acc.z += xc*wv.z; acc.w += xc*wv.w;
        }
        ks[t][j]=lrelu(acc.x); ks[t][j+1]=lrelu(acc.y); ks[t][j+2]=lrelu(acc.z); ks[t][j+3]=lrelu(acc.w);
    }
    #pragma unroll
    for (int j = 0; j < CC; j += 4){
        float4 acc = ldg4(bkv + CC + j);
        #pragma unroll
        for (int c = 0; c < CC; c++){
            float4 wv = ldg4(Wkv + c*(2*CC) + CC + j);
            float xc = xn[c];
            acc.x += xc*wv.x; acc.y += xc*wv.y; acc.z += xc*wv.z; acc.w += xc*wv.w;
        }
        vs[t][j]=lrelu(acc.x); vs[t][j+1]=lrelu(acc.y); vs[t][j+2]=lrelu(acc.z); vs[t][j+3]=lrelu(acc.w);
    }
    __syncthreads();

    // ---- attention scores + softmax (row t) ----
    float s[NT];
    float mx = -1e30f;
    #pragma unroll
    for (int m = 0; m < NT; m++){
        float acc = bsh[m*65 + t];
        #pragma unroll
        for (int c = 0; c < CC; c += 4){
            float4 kk = *reinterpret_cast<const float4*>(&ks[m][c]);
            acc += qv[c]*kk.x + qv[c+1]*kk.y + qv[c+2]*kk.z + qv[c+3]*kk.w;
        }
        s[m] = acc;
        mx = fmaxf(mx, acc);
    }
    float ssum = 0.f;
    #pragma unroll
    for (int m = 0; m < NT; m++){ s[m] = expf(s[m]-mx); ssum += s[m]; }
    float isum = 1.f/ssum;

    // ---- out = softmax @ v ----
    float o[CC];
    #pragma unroll
    for (int j = 0; j < CC; j++) o[j] = 0.f;
    #pragma unroll
    for (int m = 0; m < NT; m++){
        float p = s[m];
        #pragma unroll
        for (int j = 0; j < CC; j += 4){
            float4 vv = *reinterpret_cast<const float4*>(&vs[m][j]);
            o[j]+=p*vv.x; o[j+1]+=p*vv.y; o[j+2]+=p*vv.z; o[j+3]+=p*vv.w;
        }
    }
    #pragma unroll
    for (int j = 0; j < CC; j++) o[j] *= isum;

    // ---- proj (no activation) + residual -> x2 ----
    float x2v[CC];
    #pragma unroll
    for (int j = 0; j < CC; j += 4){
        float4 acc = ldg4(bp + j);
        #pragma unroll
        for (int c = 0; c < CC; c++){
            float4 wv = ldg4(Wp + c*CC + j);
            float oc = o[c];
            acc.x += oc*wv.x; acc.y += oc*wv.y; acc.z += oc*wv.z; acc.w += oc*wv.w;
        }
        x2v[j]=xr[j]+acc.x; x2v[j+1]=xr[j+1]+acc.y; x2v[j+2]=xr[j+2]+acc.z; x2v[j+3]=xr[j+3]+acc.w;
    }
    float* x2p = g_x2 + (size_t)tok*CC;
    #pragma unroll
    for (int j = 0; j < CC; j += 4)
        *reinterpret_cast<float4*>(x2p + j) = make_float4(x2v[j],x2v[j+1],x2v[j+2],x2v[j+3]);

    // ---- LN2 + W1 GEMM + exact GELU -> h ----
    float m2 = 0.f;
    #pragma unroll
    for (int c = 0; c < CC; c++) m2 += x2v[c];
    m2 *= (1.f/CC);
    float v2 = 0.f;
    #pragma unroll
    for (int c = 0; c < CC; c++){ float d = x2v[c]-m2; v2 += d*d; }
    v2 *= (1.f/CC);
    float rinv2 = rsqrtf(v2 + EPS);
    float y[CC];
    #pragma unroll
    for (int c = 0; c < CC; c++)
        y[c] = (x2v[c]-m2)*rinv2*__ldg(g2+c) + __ldg(beta2+c);

    float* hp = g_h + (size_t)tok*HID;
    #pragma unroll
    for (int jb = 0; jb < HID; jb += 4){
        float4 acc = ldg4(b1m + jb);
        #pragma unroll
        for (int c = 0; c < CC; c++){
            float4 wv = ldg4(W1 + c*HID + jb);
            float yc = y[c];
            acc.x += yc*wv.x; acc.y += yc*wv.y; acc.z += yc*wv.z; acc.w += yc*wv.w;
        }
        acc.x = gelu_exact(acc.x); acc.y = gelu_exact(acc.y);
        acc.z = gelu_exact(acc.z); acc.w = gelu_exact(acc.w);
        *reinterpret_cast<float4*>(hp + jb) = acc;
    }
}

// ---- kernel 2: depthwise 3x3 conv + GELU + W2 GEMM + residual ----
#define PSTR 331   // shared pixel stride (conflict-free writes across q=0..7)
__global__ __launch_bounds__(256)
void leff_kernel(const float* __restrict__ dw_k, const float* __restrict__ dw_b,
                 const float* __restrict__ W2,   const float* __restrict__ b2m,
                 float* __restrict__ out)
{
    __shared__ float sh[32*PSTR];     // [channel][halo pixel], 18x18 halo
    __shared__ float w2s[32*32];      // W2 chunk [c][o]
    __shared__ float dwks[9*32];      // dw kernel chunk [tap][c]
    __shared__ float dwbs[32];

    const int tid = threadIdx.x;
    const int tx = tid & 15, ty = tid >> 4;
    const int b  = blockIdx.z;
    const int py = blockIdx.y*16 + ty;
    const int px = blockIdx.x*16 + tx;
    const int tok = (b*HH + py)*WWD + px;

    // init accumulators with residual + output bias
    float acc[CC];
    {
        const float* x2p = g_x2 + (size_t)tok*CC;
        #pragma unroll
        for (int j = 0; j < CC; j += 4){
            float4 a = *reinterpret_cast<const float4*>(x2p + j);
            float4 bb = ldg4(b2m + j);
            acc[j]=a.x+bb.x; acc[j+1]=a.y+bb.y; acc[j+2]=a.z+bb.z; acc[j+3]=a.w+bb.w;
        }
    }

    const int gy0 = blockIdx.y*16 - 1;
    const int gx0 = blockIdx.x*16 - 1;

    for (int c0 = 0; c0 < HID; c0 += 32){
        // stage weights chunk
        if (tid < 32) dwbs[tid] = __ldg(dw_b + c0 + tid);
        for (int i = tid; i < 9*32; i += 256){
            int p = i >> 5, c = i & 31;
            dwks[i] = __ldg(dw_k + p*HID + c0 + c);
        }
        for (int i = tid; i < 32*32; i += 256)
            w2s[i] = __ldg(W2 + (c0 + (i >> 5))*CC + (i & 31));
        // stage halo tile (18x18 pixels x 32 channels), zero-padded at borders
        for (int i = tid; i < 324*8; i += 256){
            int pix = i >> 3, q = i & 7;
            int yy = gy0 + pix/18;
            int xx = gx0 + pix%18;
            float4 v4 = make_float4(0.f,0.f,0.f,0.f);
            if ((unsigned)yy < HH && (unsigned)xx < WWD)
                v4 = *reinterpret_cast<const float4*>(g_h + ((size_t)((b*HH+yy)*WWD+xx))*HID + c0 + q*4);
            int cb = q*4;
            sh[(cb+0)*PSTR+pix]=v4.x; sh[(cb+1)*PSTR+pix]=v4.y;
            sh[(cb+2)*PSTR+pix]=v4.z; sh[(cb+3)*PSTR+pix]=v4.w;
        }
        __syncthreads();

        const int p0 = ty*18 + tx;  // top-left of 3x3 stencil in halo coords
        #pragma unroll
        for (int ci = 0; ci < 32; ci++){
            const float* shc = sh + ci*PSTR;
            float cv = dwbs[ci];
            cv += shc[p0   ]*dwks[0*32+ci] + shc[p0+1 ]*dwks[1*32+ci] + shc[p0+2 ]*dwks[2*32+ci];
            cv += shc[p0+18]*dwks[3*32+ci] + shc[p0+19]*dwks[4*32+ci] + shc[p0+20]*dwks[5*32+ci];
            cv += shc[p0+36]*dwks[6*32+ci] + shc[p0+37]*dwks[7*32+ci] + shc[p0+38]*dwks[8*32+ci];
            cv = gelu_exact(cv);
            #pragma unroll
            for (int o = 0; o < CC; o += 4){
                float4 wv = *reinterpret_cast<const float4*>(w2s + ci*32 + o);
                acc[o]+=cv*wv.x; acc[o+1]+=cv*wv.y; acc[o+2]+=cv*wv.z; acc[o+3]+=cv*wv.w;
            }
        }
        __syncthreads();
    }

    float* op = out + (size_t)tok*CC;
    #pragma unroll
    for (int j = 0; j < CC; j += 4)
        *reinterpret_cast<float4*>(op + j) = make_float4(acc[j],acc[j+1],acc[j+2],acc[j+3]);
}

extern "C" void kernel_launch(void* const* d_in, const int* in_sizes, int n_in,
                              void* d_out, int out_size)
{
    const float* x     = (const float*)d_in[0];
    const float* g1    = (const float*)d_in[1];
    const float* beta1 = (const float*)d_in[2];
    const float* Wq    = (const float*)d_in[3];
    const float* bq    = (const float*)d_in[4];
    const float* Wkv   = (const float*)d_in[5];
    const float* bkv   = (const float*)d_in[6];
    const float* btab  = (const float*)d_in[7];
    const float* Wp    = (const float*)d_in[8];
    const float* bp    = (const float*)d_in[9];
    const float* g2    = (const float*)d_in[10];
    const float* beta2 = (const float*)d_in[11];
    const float* W1    = (const float*)d_in[12];
    const float* b1m   = (const float*)d_in[13];
    const float* dw_k  = (const float*)d_in[14];
    const float* dw_b  = (const float*)d_in[15];
    const float* W2    = (const float*)d_in[16];
    const float* b2m   = (const float*)d_in[17];
    const int*   ridx  = (const int*)  d_in[18];
    float* out = (float*)d_out;

    bias_kernel<<<16, 256>>>(btab, ridx);
    attn_kernel<<<BB*NWH*NWW, 64>>>(x, g1, beta1, Wq, bq, Wkv, bkv,
                                    Wp, bp, g2, beta2, W1, b1m);
    dim3 grid(WWD/16, HH/16, BB);
    leff_kernel<<<grid, 256>>>(dw_k, dw_b, W2, b2m, out);
}

// round 2
// speedup vs baseline: 1.3707x; 1.3707x over previous
#include <cuda_runtime.h>
#include <math.h>

typedef unsigned long long u64;

#define BB   2
#define HH   512
#define WWD  512
#define CC   32
#define WIN  8
#define NT   64
#define HID  128
#define NWH  64
#define NWW  64
#define NTOK (BB*HH*WWD)

#define SCALE 0.17677669529663687f
#define EPS   1e-3f

// ---- scratch ----
__device__ __align__(16) float g_x2[NTOK*CC];
__device__ __align__(16) float g_h [NTOK*HID];
__device__ __align__(16) float g_biasT[NT*NT];   // [key m][query t]

// ---- packed f32x2 helpers (sm_103a FFMA2) ----
__device__ __forceinline__ u64 pk(float a, float b){ u64 r; asm("mov.b64 %0,{%1,%2};":"=l"(r):"f"(a),"f"(b)); return r; }
__device__ __forceinline__ u64 pk1(float a){ return pk(a,a); }
__device__ __forceinline__ void upk(u64 v, float& a, float& b){ asm("mov.b64 {%0,%1},%2;":"=f"(a),"=f"(b):"l"(v)); }
__device__ __forceinline__ u64 f2fma(u64 a,u64 b,u64 c){ u64 d; asm("fma.rn.f32x2 %0,%1,%2,%3;":"=l"(d):"l"(a),"l"(b),"l"(c)); return d; }
__device__ __forceinline__ u64 f2add(u64 a,u64 b){ u64 d; asm("add.rn.f32x2 %0,%1,%2;":"=l"(d):"l"(a),"l"(b)); return d; }
__device__ __forceinline__ u64 f2mul(u64 a,u64 b){ u64 d; asm("mul.rn.f32x2 %0,%1,%2;":"=l"(d):"l"(a),"l"(b)); return d; }

__device__ __forceinline__ float lrelu(float v){ return fmaxf(v, 0.3f*v); }   // slope<1
__device__ __forceinline__ float gelu(float v){ return v * normcdff(v); }
__device__ __forceinline__ float4 ldg4(const float* p){ return __ldg(reinterpret_cast<const float4*>(p)); }

// ---- kernel 0: gather + transpose bias ----
__global__ void bias_kernel(const float* __restrict__ table, const int* __restrict__ rel_idx){
    int i = blockIdx.x*256 + threadIdx.x;
    if (i < NT*NT){
        int m = i >> 6, t = i & 63;
        g_biasT[i] = table[rel_idx[t*NT + m]];
    }
}

// ---- kernel 1: fused attention + LN2 + W1 + GELU ----
__global__ __launch_bounds__(64)
void attn_kernel(const float* __restrict__ x,
                 const float* __restrict__ g1,  const float* __restrict__ beta1,
                 const float* __restrict__ Wq,  const float* __restrict__ bq,
                 const float* __restrict__ Wkv, const float* __restrict__ bkv,
                 const float* __restrict__ Wp,  const float* __restrict__ bp,
                 const float* __restrict__ g2,  const float* __restrict__ beta2,
                 const float* __restrict__ W1,  const float* __restrict__ b1m)
{
    const int w  = blockIdx.x;
    const int t  = threadIdx.x;
    const int b  = w / (NWH*NWW);
    const int wr = w % (NWH*NWW);
    const int why = wr / NWW, wwx = wr % NWW;
    const int gy = why*WIN + (t >> 3), gx = wwx*WIN + (t & 7);
    const int tok = (b*HH + gy)*WWD + gx;

    __shared__ __align__(16) float ks[NT][36];
    __shared__ __align__(16) float vs[NT][36];

    // ---- load x (packed), LN1 ----
    const ulonglong2* xr2 = reinterpret_cast<const ulonglong2*>(x + (size_t)tok*CC);
    u64 xp[16];
    #pragma unroll
    for (int i = 0; i < 8; i++){ ulonglong2 v = __ldg(xr2+i); xp[2*i]=v.x; xp[2*i+1]=v.y; }
    u64 sa = xp[0], sb = xp[1];
    #pragma unroll
    for (int i = 2; i < 16; i += 2){ sa = f2add(sa, xp[i]); sb = f2add(sb, xp[i+1]); }
    sa = f2add(sa, sb);
    float m0, m1; upk(sa, m0, m1);
    float mean = (m0 + m1) * (1.f/32.f);
    u64 nm2 = pk1(-mean);
    u64 va = pk1(0.f), vb = pk1(0.f);
    #pragma unroll
    for (int i = 0; i < 16; i += 2){
        u64 d0 = f2add(xp[i], nm2);   va = f2fma(d0, d0, va);
        u64 d1 = f2add(xp[i+1], nm2); vb = f2fma(d1, d1, vb);
    }
    va = f2add(va, vb); upk(va, m0, m1);
    float rinv = rsqrtf((m0+m1)*(1.f/32.f) + EPS);
    u64 rin2 = pk1(rinv);

    u64 xn2[16];
    {
        const ulonglong2* gv2 = reinterpret_cast<const ulonglong2*>(g1);
        const ulonglong2* bv2 = reinterpret_cast<const ulonglong2*>(beta1);
        #pragma unroll
        for (int i = 0; i < 8; i++){
            ulonglong2 gv = __ldg(gv2+i), bv = __ldg(bv2+i);
            xn2[2*i]   = f2fma(f2mul(f2add(xp[2*i],   nm2), rin2), gv.x, bv.x);
            xn2[2*i+1] = f2fma(f2mul(f2add(xp[2*i+1], nm2), rin2), gv.y, bv.y);
        }
    }

    // ---- q = leaky(xn@Wq + bq)*SCALE ----
    u64 qv2[16];
    {
        u64 qa[16];
        const ulonglong2* bqp = reinterpret_cast<const ulonglong2*>(bq);
        #pragma unroll
        for (int i = 0; i < 8; i++){ ulonglong2 v = __ldg(bqp+i); qa[2*i]=v.x; qa[2*i+1]=v.y; }
        #pragma unroll
        for (int cp = 0; cp < 16; cp++){
            float ca, cb; upk(xn2[cp], ca, cb);
            u64 ca2 = pk1(ca), cb2 = pk1(cb);
            const ulonglong2* r0 = reinterpret_cast<const ulonglong2*>(Wq + (2*cp  )*CC);
            const ulonglong2* r1 = reinterpret_cast<const ulonglong2*>(Wq + (2*cp+1)*CC);
            #pragma unroll
            for (int j = 0; j < 8; j++){
                ulonglong2 wA = __ldg(r0+j);
                qa[2*j]   = f2fma(ca2, wA.x, qa[2*j]);
                qa[2*j+1] = f2fma(ca2, wA.y, qa[2*j+1]);
            }
            #pragma unroll
            for (int j = 0; j < 8; j++){
                ulonglong2 wB = __ldg(r1+j);
                qa[2*j]   = f2fma(cb2, wB.x, qa[2*j]);
                qa[2*j+1] = f2fma(cb2, wB.y, qa[2*j+1]);
            }
        }
        #pragma unroll
        for (int i = 0; i < 16; i++){
            float a, c; upk(qa[i], a, c);
            qv2[i] = pk(lrelu(a)*SCALE, lrelu(c)*SCALE);
        }
    }

    // ---- k, v -> shared ----
    #pragma unroll
    for (int half = 0; half < 2; half++){
        u64 ka[16];
        const ulonglong2* bkp = reinterpret_cast<const ulonglong2*>(bkv + half*CC);
        #pragma unroll
        for (int i = 0; i < 8; i++){ ulonglong2 v = __ldg(bkp+i); ka[2*i]=v.x; ka[2*i+1]=v.y; }
        #pragma unroll
        for (int cp = 0; cp < 16; cp++){
            float ca, cb; upk(xn2[cp], ca, cb);
            u64 ca2 = pk1(ca), cb2 = pk1(cb);
            const ulonglong2* r0 = reinterpret_cast<const ulonglong2*>(Wkv + (2*cp  )*(2*CC) + half*CC);
            const ulonglong2* r1 = reinterpret_cast<const ulonglong2*>(Wkv + (2*cp+1)*(2*CC) + half*CC);
            #pragma unroll
            for (int j = 0; j < 8; j++){
                ulonglong2 wA = __ldg(r0+j);
                ka[2*j]   = f2fma(ca2, wA.x, ka[2*j]);
                ka[2*j+1] = f2fma(ca2, wA.y, ka[2*j+1]);
            }
            #pragma unroll
            for (int j = 0; j < 8; j++){
                ulonglong2 wB = __ldg(r1+j);
                ka[2*j]   = f2fma(cb2, wB.x, ka[2*j]);
                ka[2*j+1] = f2fma(cb2, wB.y, ka[2*j+1]);
            }
        }
        float* dst = half ? &vs[t][0] : &ks[t][0];
        #pragma unroll
        for (int i = 0; i < 8; i++){
            float a, b2, c, d;
            upk(ka[2*i], a, b2); upk(ka[2*i+1], c, d);
            *reinterpret_cast<float4*>(dst + 4*i) =
                make_float4(lrelu(a), lrelu(b2), lrelu(c), lrelu(d));
        }
    }
    __syncthreads();

    // ---- scores + softmax ----
    float s[NT];
    float mx = -1e30f;
    #pragma unroll
    for (int m = 0; m < NT; m++){
        const ulonglong2* kr = reinterpret_cast<const ulonglong2*>(&ks[m][0]);
        u64 a0 = pk1(0.f), a1 = pk1(0.f), a2 = pk1(0.f), a3 = pk1(0.f);
        #pragma unroll
        for (int j = 0; j < 4; j++){
            ulonglong2 u = kr[2*j], v = kr[2*j+1];
            a0 = f2fma(qv2[4*j],   u.x, a0);
            a1 = f2fma(qv2[4*j+1], u.y, a1);
            a2 = f2fma(qv2[4*j+2], v.x, a2);
            a3 = f2fma(qv2[4*j+3], v.y, a3);
        }
        a0 = f2add(a0, a1); a2 = f2add(a2, a3); a0 = f2add(a0, a2);
        float lo, hi; upk(a0, lo, hi);
        float sc = lo + hi + __ldg(g_biasT + m*NT + t);
        s[m] = sc;
        mx = fmaxf(mx, sc);
    }
    float sum0 = 0.f, sum1 = 0.f;
    #pragma unroll
    for (int m = 0; m < NT; m += 2){
        s[m]   = expf(s[m]  -mx); sum0 += s[m];
        s[m+1] = expf(s[m+1]-mx); sum1 += s[m+1];
    }
    float isum = 1.f/(sum0+sum1);
    #pragma unroll
    for (int m = 0; m < NT; m++) s[m] *= isum;

    // ---- out = P @ v ----
    u64 o2[16];
    #pragma unroll
    for (int i = 0; i < 16; i++) o2[i] = pk1(0.f);
    #pragma unroll
    for (int m = 0; m < NT; m++){
        u64 p2 = pk1(s[m]);
        const ulonglong2* vr = reinterpret_cast<const ulonglong2*>(&vs[m][0]);
        #pragma unroll
        for (int j = 0; j < 8; j++){
            ulonglong2 u = vr[j];
            o2[2*j]   = f2fma(p2, u.x, o2[2*j]);
            o2[2*j+1] = f2fma(p2, u.y, o2[2*j+1]);
        }
    }

    // ---- proj + residual -> x2 ----
    u64 pa[16];
    {
        const ulonglong2* bpp = reinterpret_cast<const ulonglong2*>(bp);
        #pragma unroll
        for (int i = 0; i < 8; i++){ ulonglong2 v = __ldg(bpp+i); pa[2*i]=v.x; pa[2*i+1]=v.y; }
        #pragma unroll
        for (int cp = 0; cp < 16; cp++){
            float ca, cb; upk(o2[cp], ca, cb);
            u64 ca2 = pk1(ca), cb2 = pk1(cb);
            const ulonglong2* r0 = reinterpret_cast<const ulonglong2*>(Wp + (2*cp  )*CC);
            const ulonglong2* r1 = reinterpret_cast<const ulonglong2*>(Wp + (2*cp+1)*CC);
            #pragma unroll
            for (int j = 0; j < 8; j++){
                ulonglong2 wA = __ldg(r0+j);
                pa[2*j]   = f2fma(ca2, wA.x, pa[2*j]);
                pa[2*j+1] = f2fma(ca2, wA.y, pa[2*j+1]);
            }
            #pragma unroll
            for (int j = 0; j < 8; j++){
                ulonglong2 wB = __ldg(r1+j);
                pa[2*j]   = f2fma(cb2, wB.x, pa[2*j]);
                pa[2*j+1] = f2fma(cb2, wB.y, pa[2*j+1]);
            }
        }
        #pragma unroll
        for (int i = 0; i < 8; i++){          // reload x (L1-hot) for residual
            ulonglong2 xv = __ldg(xr2+i);
            pa[2*i]   = f2add(pa[2*i],   xv.x);
            pa[2*i+1] = f2add(pa[2*i+1], xv.y);
        }
        ulonglong2* x2o = reinterpret_cast<ulonglong2*>(g_x2 + (size_t)tok*CC);
        #pragma unroll
        for (int i = 0; i < 8; i++) x2o[i] = make_ulonglong2(pa[2*i], pa[2*i+1]);
    }

    // ---- LN2 ----
    u64 y2[16];
    {
        u64 s2a = pa[0], s2b = pa[1];
        #pragma unroll
        for (int i = 2; i < 16; i += 2){ s2a = f2add(s2a, pa[i]); s2b = f2add(s2b, pa[i+1]); }
        s2a = f2add(s2a, s2b);
        float a0, a1; upk(s2a, a0, a1);
        float mean2 = (a0+a1)*(1.f/32.f);
        u64 nm = pk1(-mean2);
        u64 v0 = pk1(0.f), v1 = pk1(0.f);
        #pragma unroll
        for (int i = 0; i < 16; i += 2){
            u64 d0 = f2add(pa[i], nm);   v0 = f2fma(d0, d0, v0);
            u64 d1 = f2add(pa[i+1], nm); v1 = f2fma(d1, d1, v1);
        }
        v0 = f2add(v0, v1); upk(v0, a0, a1);
        float ri = rsqrtf((a0+a1)*(1.f/32.f) + EPS);
        u64 ri2 = pk1(ri);
        const ulonglong2* gv2 = reinterpret_cast<const ulonglong2*>(g2);
        const ulonglong2* bv2 = reinterpret_cast<const ulonglong2*>(beta2);
        #pragma unroll
        for (int i = 0; i < 8; i++){
            ulonglong2 gv = __ldg(gv2+i), bv = __ldg(bv2+i);
            y2[2*i]   = f2fma(f2mul(f2add(pa[2*i],   nm), ri2), gv.x, bv.x);
            y2[2*i+1] = f2fma(f2mul(f2add(pa[2*i+1], nm), ri2), gv.y, bv.y);
        }
    }

    // ---- W1 + GELU -> h (4 chunks of 32 outputs) ----
    float4* hp4 = reinterpret_cast<float4*>(g_h + (size_t)tok*HID);
    #pragma unroll 1
    for (int ch = 0; ch < 4; ch++){
        u64 acc[16];
        const ulonglong2* bmp = reinterpret_cast<const ulonglong2*>(b1m + ch*32);
        #pragma unroll
        for (int i = 0; i < 8; i++){ ulonglong2 v = __ldg(bmp+i); acc[2*i]=v.x; acc[2*i+1]=v.y; }
        #pragma unroll
        for (int cp = 0; cp < 16; cp++){
            float ca, cb; upk(y2[cp], ca, cb);
            u64 ca2 = pk1(ca), cb2 = pk1(cb);
            const ulonglong2* r0 = reinterpret_cast<const ulonglong2*>(W1 + (2*cp  )*HID + ch*32);
            const ulonglong2* r1 = reinterpret_cast<const ulonglong2*>(W1 + (2*cp+1)*HID + ch*32);
            #pragma unroll
            for (int j = 0; j < 8; j++){
                ulonglong2 wA = __ldg(r0+j);
                acc[2*j]   = f2fma(ca2, wA.x, acc[2*j]);
                acc[2*j+1] = f2fma(ca2, wA.y, acc[2*j+1]);
            }
            #pragma unroll
            for (int j = 0; j < 8; j++){
                ulonglong2 wB = __ldg(r1+j);
                acc[2*j]   = f2fma(cb2, wB.x, acc[2*j]);
                acc[2*j+1] = f2fma(cb2, wB.y, acc[2*j+1]);
            }
        }
        #pragma unroll
        for (int i = 0; i < 8; i++){
            float a, b2, c, d;
            upk(acc[2*i], a, b2); upk(acc[2*i+1], c, d);
            hp4[ch*8 + i] = make_float4(gelu(a), gelu(b2), gelu(c), gelu(d));
        }
    }
}

// ---- kernel 2: depthwise conv + GELU + W2 + residual ----
#define PSTR 331
__global__ __launch_bounds__(256)
void leff_kernel(const float* __restrict__ dw_k, const float* __restrict__ dw_b,
                 const float* __restrict__ W2,   const float* __restrict__ b2m,
                 float* __restrict__ out)
{
    __shared__ __align__(16) float sh[32*PSTR];
    __shared__ __align__(16) float w2s[32*32];
    __shared__ u64 dwk2[9][16];
    __shared__ u64 dwb2[16];

    const int tid = threadIdx.x;
    const int tx = tid & 15, ty = tid >> 4;
    const int b  = blockIdx.z;
    const int py = blockIdx.y*16 + ty;
    const int px = blockIdx.x*16 + tx;
    const int tok = (b*HH + py)*WWD + px;

    u64 acc[16];
    {
        const ulonglong2* x2r = reinterpret_cast<const ulonglong2*>(g_x2 + (size_t)tok*CC);
        const ulonglong2* b2r = reinterpret_cast<const ulonglong2*>(b2m);
        #pragma unroll
        for (int i = 0; i < 8; i++){
            ulonglong2 a = __ldg(x2r+i), bb = __ldg(b2r+i);
            acc[2*i]   = f2add(a.x, bb.x);
            acc[2*i+1] = f2add(a.y, bb.y);
        }
    }

    const int gy0 = blockIdx.y*16 - 1;
    const int gx0 = blockIdx.x*16 - 1;
    const int p0  = ty*18 + tx;

    #pragma unroll 1
    for (int c0 = 0; c0 < HID; c0 += 32){
        if (tid < 16) dwb2[tid] = pk(__ldg(dw_b + c0 + 2*tid), __ldg(dw_b + c0 + 2*tid + 1));
        if (tid < 144){
            int p = tid >> 4, cp = tid & 15;
            dwk2[p][cp] = pk(__ldg(dw_k + p*HID + c0 + 2*cp), __ldg(dw_k + p*HID + c0 + 2*cp + 1));
        }
        {   // W2 chunk: [ci 0..31][o 0..31]
            int ci = tid >> 3, o4 = tid & 7;
            reinterpret_cast<float4*>(w2s)[tid] = ldg4(W2 + (c0 + ci)*CC + o4*4);
        }
        for (int i = tid; i < 324*8; i += 256){
            int pix = i >> 3, q = i & 7;
            int yy = gy0 + pix/18;
            int xx = gx0 + pix%18;
            float4 v4 = make_float4(0.f,0.f,0.f,0.f);
            if ((unsigned)yy < HH && (unsigned)xx < WWD)
                v4 = *reinterpret_cast<const float4*>(g_h + ((size_t)((b*HH+yy)*WWD+xx))*HID + c0 + q*4);
            int cb = q*4;
            sh[(cb+0)*PSTR+pix]=v4.x; sh[(cb+1)*PSTR+pix]=v4.y;
            sh[(cb+2)*PSTR+pix]=v4.z; sh[(cb+3)*PSTR+pix]=v4.w;
        }
        __syncthreads();

        #pragma unroll
        for (int cp = 0; cp < 16; cp++){
            const float* shA = sh + (2*cp)*PSTR + p0;
            const float* shB = shA + PSTR;
            u64 cv = dwb2[cp];
            cv = f2fma(pk(shA[0],  shB[0]),  dwk2[0][cp], cv);
            cv = f2fma(pk(shA[1],  shB[1]),  dwk2[1][cp], cv);
            cv = f2fma(pk(shA[2],  shB[2]),  dwk2[2][cp], cv);
            cv = f2fma(pk(shA[18], shB[18]), dwk2[3][cp], cv);
            cv = f2fma(pk(shA[19], shB[19]), dwk2[4][cp], cv);
            cv = f2fma(pk(shA[20], shB[20]), dwk2[5][cp], cv);
            cv = f2fma(pk(shA[36], shB[36]), dwk2[6][cp], cv);
            cv = f2fma(pk(shA[37], shB[37]), dwk2[7][cp], cv);
            cv = f2fma(pk(shA[38], shB[38]), dwk2[8][cp], cv);
            float a, b2; upk(cv, a, b2);
            u64 ca = pk1(gelu(a)), cb = pk1(gelu(b2));
            const ulonglong2* wA = reinterpret_cast<const ulonglong2*>(w2s + (2*cp)*32);
            const ulonglong2* wB = wA + 8;
            #pragma unroll
            for (int j = 0; j < 8; j++){
                ulonglong2 u = wA[j];
                acc[2*j]   = f2fma(ca, u.x, acc[2*j]);
                acc[2*j+1] = f2fma(ca, u.y, acc[2*j+1]);
            }
            #pragma unroll
            for (int j = 0; j < 8; j++){
                ulonglong2 u = wB[j];
                acc[2*j]   = f2fma(cb, u.x, acc[2*j]);
                acc[2*j+1] = f2fma(cb, u.y, acc[2*j+1]);
            }
        }
        __syncthreads();
    }

    ulonglong2* op = reinterpret_cast<ulonglong2*>(out + (size_t)tok*CC);
    #pragma unroll
    for (int i = 0; i < 8; i++) op[i] = make_ulonglong2(acc[2*i], acc[2*i+1]);
}

extern "C" void kernel_launch(void* const* d_in, const int* in_sizes, int n_in,
                              void* d_out, int out_size)
{
    const float* x     = (const float*)d_in[0];
    const float* g1    = (const float*)d_in[1];
    const float* beta1 = (const float*)d_in[2];
    const float* Wq    = (const float*)d_in[3];
    const float* bq    = (const float*)d_in[4];
    const float* Wkv   = (const float*)d_in[5];
    const float* bkv   = (const float*)d_in[6];
    const float* btab  = (const float*)d_in[7];
    const float* Wp    = (const float*)d_in[8];
    const float* bp    = (const float*)d_in[9];
    const float* g2    = (const float*)d_in[10];
    const float* beta2 = (const float*)d_in[11];
    const float* W1    = (const float*)d_in[12];
    const float* b1m   = (const float*)d_in[13];
    const float* dw_k  = (const float*)d_in[14];
    const float* dw_b  = (const float*)d_in[15];
    const float* W2    = (const float*)d_in[16];
    const float* b2m   = (const float*)d_in[17];
    const int*   ridx  = (const int*)  d_in[18];
    float* out = (float*)d_out;

    bias_kernel<<<16, 256>>>(btab, ridx);
    attn_kernel<<<BB*NWH*NWW, 64>>>(x, g1, beta1, Wq, bq, Wkv, bkv,
                                    Wp, bp, g2, beta2, W1, b1m);
    dim3 grid(WWD/16, HH/16, BB);
    leff_kernel<<<grid, 256>>>(dw_k, dw_b, W2, b2m, out);
}

// round 4
// speedup vs baseline: 1.9638x; 1.4328x over previous
#include <cuda_runtime.h>
#include <math.h>

typedef unsigned long long u64;

#define BB   2
#define HH   512
#define WWD  512
#define CC   32
#define WIN  8
#define NT   64
#define HID  128
#define NWH  64
#define NWW  64
#define NTOK (BB*HH*WWD)

#define SCALE 0.17677669529663687f
#define EPS   1e-3f

// ---- scratch ----
__device__ __align__(16) float g_x2[NTOK*CC];
__device__ __align__(16) float g_h [NTOK*HID];
__device__ __align__(16) float g_biasT[NT*NT];   // [key m][query t]

// ---- packed f32x2 helpers ----
__device__ __forceinline__ u64 pk(float a, float b){ u64 r; asm("mov.b64 %0,{%1,%2};":"=l"(r):"f"(a),"f"(b)); return r; }
__device__ __forceinline__ u64 pk1(float a){ return pk(a,a); }
__device__ __forceinline__ void upk(u64 v, float& a, float& b){ asm("mov.b64 {%0,%1},%2;":"=f"(a),"=f"(b):"l"(v)); }
__device__ __forceinline__ u64 f2fma(u64 a,u64 b,u64 c){ u64 d; asm("fma.rn.f32x2 %0,%1,%2,%3;":"=l"(d):"l"(a),"l"(b),"l"(c)); return d; }
__device__ __forceinline__ u64 f2add(u64 a,u64 b){ u64 d; asm("add.rn.f32x2 %0,%1,%2;":"=l"(d):"l"(a),"l"(b)); return d; }
__device__ __forceinline__ u64 f2mul(u64 a,u64 b){ u64 d; asm("mul.rn.f32x2 %0,%1,%2;":"=l"(d):"l"(a),"l"(b)); return d; }

__device__ __forceinline__ float lrelu(float v){ return fmaxf(v, 0.3f*v); }
__device__ __forceinline__ float gelu(float v){ return 0.5f*v*(1.0f + erff(v*0.70710678118654752f)); }

// ---- kernel 0: gather + transpose bias ----
__global__ void bias_kernel(const float* __restrict__ table, const int* __restrict__ rel_idx){
    int i = blockIdx.x*256 + threadIdx.x;
    if (i < NT*NT){
        int m = i >> 6, t = i & 63;
        g_biasT[i] = table[rel_idx[t*NT + m]];
    }
}

// shared layout offsets (floats) for attn
#define OFF_WQ   0
#define OFF_WKV  1024
#define OFF_WP   3072
#define OFF_W1   4096
#define OFF_BQ   8192
#define OFF_BKV  8224
#define OFF_BP   8288
#define OFF_B1M  8320
#define OFF_G1   8448
#define OFF_BE1  8480
#define OFF_G2   8512
#define OFF_BE2  8544
#define OFF_KV   8576
#define ATTN_SMEM_FLOATS (8576 + 2*2*2304)   // + 2 windows * (ks+vs) of 64*36
#define ATTN_SMEM_BYTES  (ATTN_SMEM_FLOATS*4)

__device__ __forceinline__ void stage(float* dst, const float* src, int n4, int tid, int nt){
    const float4* s = reinterpret_cast<const float4*>(src);
    float4* d = reinterpret_cast<float4*>(dst);
    for (int i = tid; i < n4; i += nt) d[i] = __ldg(s + i);
}

// ---- kernel 1: fused attention + LN2 + W1 + GELU (2 windows / 128 threads) ----
__global__ __launch_bounds__(128)
void attn_kernel(const float* __restrict__ x,
                 const float* __restrict__ g1,  const float* __restrict__ beta1,
                 const float* __restrict__ Wq,  const float* __restrict__ bq,
                 const float* __restrict__ Wkv, const float* __restrict__ bkv,
                 const float* __restrict__ Wp,  const float* __restrict__ bp,
                 const float* __restrict__ g2,  const float* __restrict__ beta2,
                 const float* __restrict__ W1,  const float* __restrict__ b1m)
{
    extern __shared__ __align__(16) float sm[];
    const int tid = threadIdx.x;
    const int wi  = tid >> 6;            // window within block
    const int t   = tid & 63;            // token within window

    // ---- stage weights/biases ----
    stage(sm+OFF_WQ,  Wq,  256, tid, 128);
    stage(sm+OFF_WKV, Wkv, 512, tid, 128);
    stage(sm+OFF_WP,  Wp,  256, tid, 128);
    stage(sm+OFF_W1,  W1, 1024, tid, 128);
    stage(sm+OFF_BQ,  bq,    8, tid, 128);
    stage(sm+OFF_BKV, bkv,  16, tid, 128);
    stage(sm+OFF_BP,  bp,    8, tid, 128);
    stage(sm+OFF_B1M, b1m,  32, tid, 128);
    stage(sm+OFF_G1,  g1,    8, tid, 128);
    stage(sm+OFF_BE1, beta1, 8, tid, 128);
    stage(sm+OFF_G2,  g2,    8, tid, 128);
    stage(sm+OFF_BE2, beta2, 8, tid, 128);

    const int w  = blockIdx.x*2 + wi;
    const int b  = w / (NWH*NWW);
    const int wr = w % (NWH*NWW);
    const int why = wr / NWW, wwx = wr % NWW;
    const int gy = why*WIN + (t >> 3), gx = wwx*WIN + (t & 7);
    const int tok = (b*HH + gy)*WWD + gx;

    float* ksw = sm + OFF_KV + wi*4608;      // [64][36]
    float* vsw = ksw + 2304;

    // ---- load x, LN1 ----
    const ulonglong2* xr2 = reinterpret_cast<const ulonglong2*>(x + (size_t)tok*CC);
    u64 xp[16];
    #pragma unroll
    for (int i = 0; i < 8; i++){ ulonglong2 v = __ldg(xr2+i); xp[2*i]=v.x; xp[2*i+1]=v.y; }
    u64 sa = xp[0], sb = xp[1];
    #pragma unroll
    for (int i = 2; i < 16; i += 2){ sa = f2add(sa, xp[i]); sb = f2add(sb, xp[i+1]); }
    sa = f2add(sa, sb);
    float m0, m1; upk(sa, m0, m1);
    float mean = (m0 + m1) * (1.f/32.f);
    u64 nm2 = pk1(-mean);
    u64 va = pk1(0.f), vb = pk1(0.f);
    #pragma unroll
    for (int i = 0; i < 16; i += 2){
        u64 d0 = f2add(xp[i], nm2);   va = f2fma(d0, d0, va);
        u64 d1 = f2add(xp[i+1], nm2); vb = f2fma(d1, d1, vb);
    }
    va = f2add(va, vb); upk(va, m0, m1);
    float rinv = rsqrtf((m0+m1)*(1.f/32.f) + EPS);
    u64 rin2 = pk1(rinv);

    __syncthreads();   // weights staged

    u64 xn2[16];
    {
        const ulonglong2* gv2 = reinterpret_cast<const ulonglong2*>(sm+OFF_G1);
        const ulonglong2* bv2 = reinterpret_cast<const ulonglong2*>(sm+OFF_BE1);
        #pragma unroll
        for (int i = 0; i < 8; i++){
            ulonglong2 gv = gv2[i], bv = bv2[i];
            xn2[2*i]   = f2fma(f2mul(f2add(xp[2*i],   nm2), rin2), gv.x, bv.x);
            xn2[2*i+1] = f2fma(f2mul(f2add(xp[2*i+1], nm2), rin2), gv.y, bv.y);
        }
    }

    // ---- q ----
    u64 qv2[16];
    {
        u64 qa[16];
        const ulonglong2* bqp = reinterpret_cast<const ulonglong2*>(sm+OFF_BQ);
        #pragma unroll
        for (int i = 0; i < 8; i++){ ulonglong2 v = bqp[i]; qa[2*i]=v.x; qa[2*i+1]=v.y; }
        #pragma unroll
        for (int cp = 0; cp < 16; cp++){
            float ca, cb; upk(xn2[cp], ca, cb);
            u64 ca2 = pk1(ca), cb2 = pk1(cb);
            const ulonglong2* r0 = reinterpret_cast<const ulonglong2*>(sm+OFF_WQ + (2*cp  )*CC);
            const ulonglong2* r1 = reinterpret_cast<const ulonglong2*>(sm+OFF_WQ + (2*cp+1)*CC);
            #pragma unroll
            for (int j = 0; j < 8; j++){
                ulonglong2 wA = r0[j];
                qa[2*j]   = f2fma(ca2, wA.x, qa[2*j]);
                qa[2*j+1] = f2fma(ca2, wA.y, qa[2*j+1]);
            }
            #pragma unroll
            for (int j = 0; j < 8; j++){
                ulonglong2 wB = r1[j];
                qa[2*j]   = f2fma(cb2, wB.x, qa[2*j]);
                qa[2*j+1] = f2fma(cb2, wB.y, qa[2*j+1]);
            }
        }
        #pragma unroll
        for (int i = 0; i < 16; i++){
            float a, c; upk(qa[i], a, c);
            qv2[i] = pk(lrelu(a)*SCALE, lrelu(c)*SCALE);
        }
    }

    // ---- k, v -> shared ----
    #pragma unroll
    for (int half = 0; half < 2; half++){
        u64 ka[16];
        const ulonglong2* bkp = reinterpret_cast<const ulonglong2*>(sm+OFF_BKV + half*CC);
        #pragma unroll
        for (int i = 0; i < 8; i++){ ulonglong2 v = bkp[i]; ka[2*i]=v.x; ka[2*i+1]=v.y; }
        #pragma unroll
        for (int cp = 0; cp < 16; cp++){
            float ca, cb; upk(xn2[cp], ca, cb);
            u64 ca2 = pk1(ca), cb2 = pk1(cb);
            const ulonglong2* r0 = reinterpret_cast<const ulonglong2*>(sm+OFF_WKV + (2*cp  )*(2*CC) + half*CC);
            const ulonglong2* r1 = reinterpret_cast<const ulonglong2*>(sm+OFF_WKV + (2*cp+1)*(2*CC) + half*CC);
            #pragma unroll
            for (int j = 0; j < 8; j++){
                ulonglong2 wA = r0[j];
                ka[2*j]   = f2fma(ca2, wA.x, ka[2*j]);
                ka[2*j+1] = f2fma(ca2, wA.y, ka[2*j+1]);
            }
            #pragma unroll
            for (int j = 0; j < 8; j++){
                ulonglong2 wB = r1[j];
                ka[2*j]   = f2fma(cb2, wB.x, ka[2*j]);
                ka[2*j+1] = f2fma(cb2, wB.y, ka[2*j+1]);
            }
        }
        float* dst = (half ? vsw : ksw) + t*36;
        #pragma unroll
        for (int i = 0; i < 8; i++){
            float a, b2, c, d;
            upk(ka[2*i], a, b2); upk(ka[2*i+1], c, d);
            *reinterpret_cast<float4*>(dst + 4*i) =
                make_float4(lrelu(a), lrelu(b2), lrelu(c), lrelu(d));
        }
    }
    __syncthreads();

    // ---- scores + softmax ----
    float s[NT];
    float mx = -1e30f;
    #pragma unroll
    for (int m = 0; m < NT; m++){
        const ulonglong2* kr = reinterpret_cast<const ulonglong2*>(ksw + m*36);
        u64 a0 = pk1(0.f), a1 = pk1(0.f), a2 = pk1(0.f), a3 = pk1(0.f);
        #pragma unroll
        for (int j = 0; j < 4; j++){
            ulonglong2 u = kr[2*j], v = kr[2*j+1];
            a0 = f2fma(qv2[4*j],   u.x, a0);
            a1 = f2fma(qv2[4*j+1], u.y, a1);
            a2 = f2fma(qv2[4*j+2], v.x, a2);
            a3 = f2fma(qv2[4*j+3], v.y, a3);
        }
        a0 = f2add(a0, a1); a2 = f2add(a2, a3); a0 = f2add(a0, a2);
        float lo, hi; upk(a0, lo, hi);
        float sc = lo + hi + __ldg(g_biasT + m*NT + t);
        s[m] = sc;
        mx = fmaxf(mx, sc);
    }
    float sum0 = 0.f, sum1 = 0.f;
    #pragma unroll
    for (int m = 0; m < NT; m += 2){
        s[m]   = __expf(s[m]  -mx); sum0 += s[m];
        s[m+1] = __expf(s[m+1]-mx); sum1 += s[m+1];
    }
    float isum = 1.f/(sum0+sum1);
    #pragma unroll
    for (int m = 0; m < NT; m++) s[m] *= isum;

    // ---- out = P @ v ----
    u64 o2[16];
    #pragma unroll
    for (int i = 0; i < 16; i++) o2[i] = pk1(0.f);
    #pragma unroll
    for (int m = 0; m < NT; m++){
        u64 p2 = pk1(s[m]);
        const ulonglong2* vr = reinterpret_cast<const ulonglong2*>(vsw + m*36);
        #pragma unroll
        for (int j = 0; j < 8; j++){
            ulonglong2 u = vr[j];
            o2[2*j]   = f2fma(p2, u.x, o2[2*j]);
            o2[2*j+1] = f2fma(p2, u.y, o2[2*j+1]);
        }
    }

    // ---- proj + residual -> x2 ----
    u64 pa[16];
    {
        const ulonglong2* bpp = reinterpret_cast<const ulonglong2*>(sm+OFF_BP);
        #pragma unroll
        for (int i = 0; i < 8; i++){ ulonglong2 v = bpp[i]; pa[2*i]=v.x; pa[2*i+1]=v.y; }
        #pragma unroll
        for (int cp = 0; cp < 16; cp++){
            float ca, cb; upk(o2[cp], ca, cb);
            u64 ca2 = pk1(ca), cb2 = pk1(cb);
            const ulonglong2* r0 = reinterpret_cast<const ulonglong2*>(sm+OFF_WP + (2*cp  )*CC);
            const ulonglong2* r1 = reinterpret_cast<const ulonglong2*>(sm+OFF_WP + (2*cp+1)*CC);
            #pragma unroll
            for (int j = 0; j < 8; j++){
                ulonglong2 wA = r0[j];
                pa[2*j]   = f2fma(ca2, wA.x, pa[2*j]);
                pa[2*j+1] = f2fma(ca2, wA.y, pa[2*j+1]);
            }
            #pragma unroll
            for (int j = 0; j < 8; j++){
                ulonglong2 wB = r1[j];
                pa[2*j]   = f2fma(cb2, wB.x, pa[2*j]);
                pa[2*j+1] = f2fma(cb2, wB.y, pa[2*j+1]);
            }
        }
        #pragma unroll
        for (int i = 0; i < 8; i++){
            ulonglong2 xv = __ldg(xr2+i);
            pa[2*i]   = f2add(pa[2*i],   xv.x);
            pa[2*i+1] = f2add(pa[2*i+1], xv.y);
        }
        ulonglong2* x2o = reinterpret_cast<ulonglong2*>(g_x2 + (size_t)tok*CC);
        #pragma unroll
        for (int i = 0; i < 8; i++) x2o[i] = make_ulonglong2(pa[2*i], pa[2*i+1]);
    }

    // ---- LN2 ----
    u64 y2[16];
    {
        u64 s2a = pa[0], s2b = pa[1];
        #pragma unroll
        for (int i = 2; i < 16; i += 2){ s2a = f2add(s2a, pa[i]); s2b = f2add(s2b, pa[i+1]); }
        s2a = f2add(s2a, s2b);
        float a0, a1; upk(s2a, a0, a1);
        float mean2 = (a0+a1)*(1.f/32.f);
        u64 nm = pk1(-mean2);
        u64 v0 = pk1(0.f), v1 = pk1(0.f);
        #pragma unroll
        for (int i = 0; i < 16; i += 2){
            u64 d0 = f2add(pa[i], nm);   v0 = f2fma(d0, d0, v0);
            u64 d1 = f2add(pa[i+1], nm); v1 = f2fma(d1, d1, v1);
        }
        v0 = f2add(v0, v1); upk(v0, a0, a1);
        float ri = rsqrtf((a0+a1)*(1.f/32.f) + EPS);
        u64 ri2 = pk1(ri);
        const ulonglong2* gv2 = reinterpret_cast<const ulonglong2*>(sm+OFF_G2);
        const ulonglong2* bv2 = reinterpret_cast<const ulonglong2*>(sm+OFF_BE2);
        #pragma unroll
        for (int i = 0; i < 8; i++){
            ulonglong2 gv = gv2[i], bv = bv2[i];
            y2[2*i]   = f2fma(f2mul(f2add(pa[2*i],   nm), ri2), gv.x, bv.x);
            y2[2*i+1] = f2fma(f2mul(f2add(pa[2*i+1], nm), ri2), gv.y, bv.y);
        }
    }

    // ---- W1 + GELU -> h ----
    float4* hp4 = reinterpret_cast<float4*>(g_h + (size_t)tok*HID);
    #pragma unroll 1
    for (int ch = 0; ch < 4; ch++){
        u64 acc[16];
        const ulonglong2* bmp = reinterpret_cast<const ulonglong2*>(sm+OFF_B1M + ch*32);
        #pragma unroll
        for (int i = 0; i < 8; i++){ ulonglong2 v = bmp[i]; acc[2*i]=v.x; acc[2*i+1]=v.y; }
        #pragma unroll
        for (int cp = 0; cp < 16; cp++){
            float ca, cb; upk(y2[cp], ca, cb);
            u64 ca2 = pk1(ca), cb2 = pk1(cb);
            const ulonglong2* r0 = reinterpret_cast<const ulonglong2*>(sm+OFF_W1 + (2*cp  )*HID + ch*32);
            const ulonglong2* r1 = reinterpret_cast<const ulonglong2*>(sm+OFF_W1 + (2*cp+1)*HID + ch*32);
            #pragma unroll
            for (int j = 0; j < 8; j++){
                ulonglong2 wA = r0[j];
                acc[2*j]   = f2fma(ca2, wA.x, acc[2*j]);
                acc[2*j+1] = f2fma(ca2, wA.y, acc[2*j+1]);
            }
            #pragma unroll
            for (int j = 0; j < 8; j++){
                ulonglong2 wB = r1[j];
                acc[2*j]   = f2fma(cb2, wB.x, acc[2*j]);
                acc[2*j+1] = f2fma(cb2, wB.y, acc[2*j+1]);
            }
        }
        #pragma unroll
        for (int i = 0; i < 8; i++){
            float a, b2, c, d;
            upk(acc[2*i], a, b2); upk(acc[2*i+1], c, d);
            hp4[ch*8 + i] = make_float4(gelu(a), gelu(b2), gelu(c), gelu(d));
        }
    }
}

// ---- kernel 2: depthwise conv + GELU + W2 + residual ----
// dynamic smem: sh [324*34] floats (pixel-major, 8B-aligned ops only),
//               w2s [1024], dwk2 u64[144], dwb2 u64[16]
#define LEFF_SH      0
#define LEFF_W2S     (324*34)                // 11016
#define LEFF_DWK     (LEFF_W2S + 1024)       // floats; u64 area
#define LEFF_DWB     (LEFF_DWK + 288)        // 144 u64 = 288 floats
#define LEFF_SMEM_FLOATS (LEFF_DWB + 32)
#define LEFF_SMEM_BYTES  (LEFF_SMEM_FLOATS*4)

__global__ __launch_bounds__(256)
void leff_kernel(const float* __restrict__ dw_k, const float* __restrict__ dw_b,
                 const float* __restrict__ W2,   const float* __restrict__ b2m,
                 float* __restrict__ out)
{
    extern __shared__ __align__(16) float sm[];
    float* sh  = sm + LEFF_SH;     // [pix][34] pixel-major
    float* w2s = sm + LEFF_W2S;
    u64*  dwk2 = reinterpret_cast<u64*>(sm + LEFF_DWK);  // [9][16]
    u64*  dwb2 = reinterpret_cast<u64*>(sm + LEFF_DWB);

    const int tid = threadIdx.x;
    const int tx = tid & 15, ty = tid >> 4;
    const int b  = blockIdx.z;
    const int py = blockIdx.y*16 + ty;
    const int px = blockIdx.x*16 + tx;
    const int tok = (b*HH + py)*WWD + px;

    u64 acc[16];
    {
        const ulonglong2* x2r = reinterpret_cast<const ulonglong2*>(g_x2 + (size_t)tok*CC);
        const ulonglong2* b2r = reinterpret_cast<const ulonglong2*>(b2m);
        #pragma unroll
        for (int i = 0; i < 8; i++){
            ulonglong2 a = __ldg(x2r+i), bb = __ldg(b2r+i);
            acc[2*i]   = f2add(a.x, bb.x);
            acc[2*i+1] = f2add(a.y, bb.y);
        }
    }

    const int gy0 = blockIdx.y*16 - 1;
    const int gx0 = blockIdx.x*16 - 1;
    const int p0  = ty*18 + tx;

    #pragma unroll 1
    for (int c0 = 0; c0 < HID; c0 += 32){
        if (tid < 16) dwb2[tid] = pk(__ldg(dw_b + c0 + 2*tid), __ldg(dw_b + c0 + 2*tid + 1));
        if (tid < 144){
            int p = tid >> 4, cp = tid & 15;
            dwk2[p*16+cp] = pk(__ldg(dw_k + p*HID + c0 + 2*cp), __ldg(dw_k + p*HID + c0 + 2*cp + 1));
        }
        {
            int ci = tid >> 3, o4 = tid & 7;
            reinterpret_cast<float4*>(w2s)[tid] =
                __ldg(reinterpret_cast<const float4*>(W2 + (c0 + ci)*CC + o4*4));
        }
        for (int i = tid; i < 324*8; i += 256){
            int pix = i >> 3, q = i & 7;
            int yy = gy0 + pix/18;
            int xx = gx0 + pix%18;
            ulonglong2 v2 = make_ulonglong2(0ull, 0ull);   // fp32 zeros
            if ((unsigned)yy < HH && (unsigned)xx < WWD)
                v2 = __ldg(reinterpret_cast<const ulonglong2*>(
                        g_h + ((size_t)((b*HH+yy)*WWD+xx))*HID + c0 + q*4));
            // pixel stride 34 floats = 136B: only 8B-aligned -> two STS.64
            u64* dst = reinterpret_cast<u64*>(sh + pix*34 + q*4);
            dst[0] = v2.x;
            dst[1] = v2.y;
        }
        __syncthreads();

        #pragma unroll
        for (int cp = 0; cp < 16; cp++){
            const u64* s0 = reinterpret_cast<const u64*>(sh + p0*34 + 2*cp);
            u64 cv = dwb2[cp];
            cv = f2fma(s0[0*17+0],  dwk2[0*16+cp], cv);
            cv = f2fma(s0[0*17+17], dwk2[1*16+cp], cv);
            cv = f2fma(s0[0*17+34], dwk2[2*16+cp], cv);
            cv = f2fma(s0[9*34+0],  dwk2[3*16+cp], cv);
            cv = f2fma(s0[9*34+17], dwk2[4*16+cp], cv);
            cv = f2fma(s0[9*34+34], dwk2[5*16+cp], cv);
            cv = f2fma(s0[18*34+0], dwk2[6*16+cp], cv);
            cv = f2fma(s0[18*34+17],dwk2[7*16+cp], cv);
            cv = f2fma(s0[18*34+34],dwk2[8*16+cp], cv);
            float a, b2; upk(cv, a, b2);
            u64 ca = pk1(gelu(a)), cb = pk1(gelu(b2));
            const ulonglong2* wA = reinterpret_cast<const ulonglong2*>(w2s + (2*cp)*32);
            const ulonglong2* wB = wA + 8;
            #pragma unroll
            for (int j = 0; j < 8; j++){
                ulonglong2 u = wA[j];
                acc[2*j]   = f2fma(ca, u.x, acc[2*j]);
                acc[2*j+1] = f2fma(ca, u.y, acc[2*j+1]);
            }
            #pragma unroll
            for (int j = 0; j < 8; j++){
                ulonglong2 u = wB[j];
                acc[2*j]   = f2fma(cb, u.x, acc[2*j]);
                acc[2*j+1] = f2fma(cb, u.y, acc[2*j+1]);
            }
        }
        __syncthreads();
    }

    ulonglong2* op = reinterpret_cast<ulonglong2*>(out + (size_t)tok*CC);
    #pragma unroll
    for (int i = 0; i < 8; i++) op[i] = make_ulonglong2(acc[2*i], acc[2*i+1]);
}

extern "C" void kernel_launch(void* const* d_in, const int* in_sizes, int n_in,
                              void* d_out, int out_size)
{
    const float* x     = (const float*)d_in[0];
    const float* g1    = (const float*)d_in[1];
    const float* beta1 = (const float*)d_in[2];
    const float* Wq    = (const float*)d_in[3];
    const float* bq    = (const float*)d_in[4];
    const float* Wkv   = (const float*)d_in[5];
    const float* bkv   = (const float*)d_in[6];
    const float* btab  = (const float*)d_in[7];
    const float* Wp    = (const float*)d_in[8];
    const float* bp    = (const float*)d_in[9];
    const float* g2    = (const float*)d_in[10];
    const float* beta2 = (const float*)d_in[11];
    const float* W1    = (const float*)d_in[12];
    const float* b1m   = (const float*)d_in[13];
    const float* dw_k  = (const float*)d_in[14];
    const float* dw_b  = (const float*)d_in[15];
    const float* W2    = (const float*)d_in[16];
    const float* b2m   = (const float*)d_in[17];
    const int*   ridx  = (const int*)  d_in[18];
    float* out = (float*)d_out;

    cudaFuncSetAttribute(attn_kernel, cudaFuncAttributeMaxDynamicSharedMemorySize, ATTN_SMEM_BYTES);
    cudaFuncSetAttribute(leff_kernel, cudaFuncAttributeMaxDynamicSharedMemorySize, LEFF_SMEM_BYTES);

    bias_kernel<<<16, 256>>>(btab, ridx);
    attn_kernel<<<BB*NWH*NWW/2, 128, ATTN_SMEM_BYTES>>>(x, g1, beta1, Wq, bq, Wkv, bkv,
                                                        Wp, bp, g2, beta2, W1, b1m);
    dim3 grid(WWD/16, HH/16, BB);
    leff_kernel<<<grid, 256, LEFF_SMEM_BYTES>>>(dw_k, dw_b, W2, b2m, out);
}